// round 15
// baseline (speedup 1.0000x reference)
#include <cuda_runtime.h>
#include <stdint.h>

#define IN_F   4096
#define OUT_F  4096
#define RANK   8
#define MAX_TOKENS 8192
#define KSPLIT 8
#define KRANGE (IN_F / KSPLIT)     // 512 per warp
#define CHUNK_K 128                // staged K per chunk (512B/row bursts)
#define NCHUNK (KRANGE / CHUNK_K)  // 4
#define XROW 132                   // 128 + 4 pad (conflict-free A frags)

__device__ float    g_t[MAX_TOKENS * RANK];
__device__ uint32_t g_c1hi[IN_F * RANK];                 // c1^T as tf32 hi
__device__ uint32_t g_c1lo[IN_F * RANK];                 // c1^T as tf32 lo

__device__ __forceinline__ uint32_t f2tf32(float v) {
    uint32_t r;
    asm("cvt.rna.tf32.f32 %0, %1;" : "=r"(r) : "f"(v));
    return r;
}

__device__ __forceinline__ void mma_tf32(float acc[4], const uint32_t a[4],
                                         const uint32_t b[2]) {
    asm("mma.sync.aligned.m16n8k8.row.col.f32.tf32.tf32.f32 "
        "{%0,%1,%2,%3},{%4,%5,%6,%7},{%8,%9},{%0,%1,%2,%3};"
        : "+f"(acc[0]), "+f"(acc[1]), "+f"(acc[2]), "+f"(acc[3])
        : "r"(a[0]), "r"(a[1]), "r"(a[2]), "r"(a[3]),
          "r"(b[0]), "r"(b[1]));
}

// ---------------------------------------------------------------------------
// Prep: c1[r][i] -> transposed tf32 hi/lo arrays c1t[i][r].
// ---------------------------------------------------------------------------
__global__ void __launch_bounds__(256) tt_prep(const float* __restrict__ c1) {
    const int idx = blockIdx.x * 256 + threadIdx.x;   // = i*8 + r
    const int i = idx >> 3, r = idx & 7;
    const float v = c1[(size_t)r * IN_F + i];
    const uint32_t hi = f2tf32(v);
    g_c1hi[idx] = hi;
    g_c1lo[idx] = f2tf32(v - __uint_as_float(hi));
}

// ---------------------------------------------------------------------------
// Stage 1 (tensor, burst-staged): t = x @ c1^T via m16n8k8 tf32.
// Block = 8 warps = one 16-token tile; warp w owns K-range [w*512,(w+1)*512),
// walked in 4 chunks of k128. STAGING IS THE POINT: per staging instruction
// the whole warp fetches ONE row's contiguous 512B (lane l -> float4 l), so
// DRAM sees long per-row bursts instead of 128B slivers from 64K streams.
// A-frags from padded smem (bank 4g+tig+koff: conflict-free). Partials
// combined in-block -> g_t (g_part roundtrip deleted).
// ---------------------------------------------------------------------------
__global__ void __launch_bounds__(256) tt_stage1(const float* __restrict__ x) {
    __shared__ float xs[KSPLIT][16 * XROW];     // 67.6 KB
    __shared__ float part[KSPLIT][16][RANK];    // 4 KB

    const int w    = threadIdx.x >> 5;
    const int lane = threadIdx.x & 31;
    const int g    = lane >> 2;                 // 0..7
    const int tig  = lane & 3;                  // 0..3
    const int token0 = blockIdx.x * 16;
    const int k0 = w * KRANGE;

    float* xw = xs[w];
    const float4* xg = reinterpret_cast<const float4*>(x);

    float acc[4] = {0.f, 0.f, 0.f, 0.f};

    for (int c = 0; c < NCHUNK; c++) {
        const int kc = k0 + c * CHUNK_K;

        // Stage 16 rows x 512B; instruction j = one full row burst.
#pragma unroll 4
        for (int j = 0; j < 16; j++) {
            const float4 v = xg[(size_t)(token0 + j) * (IN_F / 4) + (kc >> 2) + lane];
            *reinterpret_cast<float4*>(&xw[j * XROW + lane * 4]) = v;
        }
        __syncwarp();

#pragma unroll
        for (int ks = 0; ks < CHUNK_K / 8; ks++) {
            const int koff = ks * 8;
            const float r0 = xw[g * XROW + koff + tig];
            const float r1 = xw[(g + 8) * XROW + koff + tig];
            const float r2 = xw[g * XROW + koff + tig + 4];
            const float r3 = xw[(g + 8) * XROW + koff + tig + 4];

            uint32_t ahi[4], alo[4];
            ahi[0] = f2tf32(r0); ahi[1] = f2tf32(r1);
            ahi[2] = f2tf32(r2); ahi[3] = f2tf32(r3);
            alo[0] = f2tf32(r0 - __uint_as_float(ahi[0]));
            alo[1] = f2tf32(r1 - __uint_as_float(ahi[1]));
            alo[2] = f2tf32(r2 - __uint_as_float(ahi[2]));
            alo[3] = f2tf32(r3 - __uint_as_float(ahi[3]));

            const int bi0 = (kc + koff + tig) * RANK + g;
            const int bi1 = (kc + koff + tig + 4) * RANK + g;
            const uint32_t bhi[2] = { __ldg(&g_c1hi[bi0]), __ldg(&g_c1hi[bi1]) };
            const uint32_t blo[2] = { __ldg(&g_c1lo[bi0]), __ldg(&g_c1lo[bi1]) };

            mma_tf32(acc, ahi, bhi);
            mma_tf32(acc, ahi, blo);
            mma_tf32(acc, alo, bhi);
        }
        __syncwarp();
    }

    // Deposit warp partials; C frag: c0=(g,2t) c1=(g,2t+1) c2,c3=(g+8,..)
    part[w][g][2 * tig]         = acc[0];
    part[w][g][2 * tig + 1]     = acc[1];
    part[w][g + 8][2 * tig]     = acc[2];
    part[w][g + 8][2 * tig + 1] = acc[3];
    __syncthreads();

    // 128 threads combine the 8 K-split partials -> g_t (coalesced)
    if (threadIdx.x < 16 * RANK) {
        const int tl = threadIdx.x >> 3;
        const int r  = threadIdx.x & 7;
        float s = 0.f;
#pragma unroll
        for (int p = 0; p < KSPLIT; p++) s += part[p][tl][r];
        g_t[(size_t)(token0 + tl) * RANK + r] = s;
    }
}

// ---------------------------------------------------------------------------
// Stage 2: y[tok, o] = bias[o] + sum_r t[tok, r] * core0[o, r]
// Best-known body (25.6us): 64 tokens x 1024 outputs per block, t via
// LDS.128 float4 pairs, c0 coeffs in regs, STG.128 evict-first stores.
// ---------------------------------------------------------------------------
__global__ void __launch_bounds__(256) tt_stage2(const float* __restrict__ c0,
                                                 const float* __restrict__ bias,
                                                 float* __restrict__ y) {
    __shared__ float4 ts[64 * 2];
    const int tid = threadIdx.x;
    const int token0 = blockIdx.y * 64;
    const int o = blockIdx.x * 1024 + tid * 4;

    if (tid < 128) {
        const float4* tg = reinterpret_cast<const float4*>(g_t + (size_t)token0 * RANK);
        ts[tid] = tg[tid];
    }

    float4 ca[4], cb[4];
#pragma unroll
    for (int j = 0; j < 4; j++) {
        const float4* c = reinterpret_cast<const float4*>(c0 + (size_t)(o + j) * RANK);
        ca[j] = __ldg(c);
        cb[j] = __ldg(c + 1);
    }
    const float4 bv = __ldg(reinterpret_cast<const float4*>(bias + o));

    __syncthreads();

#pragma unroll 4
    for (int tok = 0; tok < 64; tok++) {
        const float4 tA = ts[tok * 2];
        const float4 tB = ts[tok * 2 + 1];

        float4 res;
        res.x = bv.x + ca[0].x * tA.x + ca[0].y * tA.y + ca[0].z * tA.z + ca[0].w * tA.w
                     + cb[0].x * tB.x + cb[0].y * tB.y + cb[0].z * tB.z + cb[0].w * tB.w;
        res.y = bv.y + ca[1].x * tA.x + ca[1].y * tA.y + ca[1].z * tA.z + ca[1].w * tA.w
                     + cb[1].x * tB.x + cb[1].y * tB.y + cb[1].z * tB.z + cb[1].w * tB.w;
        res.z = bv.z + ca[2].x * tA.x + ca[2].y * tA.y + ca[2].z * tA.z + ca[2].w * tA.w
                     + cb[2].x * tB.x + cb[2].y * tB.y + cb[2].z * tB.z + cb[2].w * tB.w;
        res.w = bv.w + ca[3].x * tA.x + ca[3].y * tA.y + ca[3].z * tA.z + ca[3].w * tA.w
                     + cb[3].x * tB.x + cb[3].y * tB.y + cb[3].z * tB.z + cb[3].w * tB.w;

        __stcs(reinterpret_cast<float4*>(y + (size_t)(token0 + tok) * OUT_F + o),
               res);
    }
}

extern "C" void kernel_launch(void* const* d_in, const int* in_sizes, int n_in,
                              void* d_out, int out_size) {
    const float* x    = (const float*)d_in[0];   // [TOKENS, IN_F]
    const float* c0   = (const float*)d_in[1];   // [OUT_F, RANK]
    const float* c1   = (const float*)d_in[2];   // [RANK, IN_F]
    const float* bias = (const float*)d_in[3];   // [OUT_F]
    float* y = (float*)d_out;

    const int tokens = in_sizes[0] / IN_F;       // 8192

    tt_prep<<<(IN_F * RANK) / 256, 256>>>(c1);

    // Stage 1: one 16-token tile per block, 8 K-split warps -> 512 blocks
    tt_stage1<<<tokens / 16, 256>>>(x);

    // Stage 2: 4 output chunks x 64-token groups = 512 blocks
    dim3 g2(OUT_F / 1024, tokens / 64);
    tt_stage2<<<g2, 256>>>(c0, bias, y);
}

// round 16
// speedup vs baseline: 1.0933x; 1.0933x over previous
#include <cuda_runtime.h>

#define IN_F   4096
#define OUT_F  4096
#define RANK   8
#define MAX_TOKENS 8192

// Intermediate t[tok][r] = x @ core1^T  (256 KB, lives in L2)
__device__ float g_t[MAX_TOKENS * RANK];

// ---------------------------------------------------------------------------
// Stage 1: t[tok, r] = sum_i x[tok, i] * core1[r, i]
// EXACT round-6 structure (best stage1: 41.1us): 128 threads = 4 warps
// covering the same 4 tokens; warp w reduces i-quarter [w*1024,(w+1)*1024).
// SINGLE CHANGE: x loads use __ldcv (no L1/L2 allocate). Rationale: x is a
// 128MB single-use stream vs 126MB L2 -> read-allocate is pure thrash, and
// the documented LTS-cap path (B300_MICROARCH ~6300 B/cyc) is LDG.cv.
// r12 already showed cache-op monotonicity: default 45.6 > ldcs 41.1 > cv ?
// ---------------------------------------------------------------------------
__global__ void __launch_bounds__(128) tt_stage1(const float* __restrict__ x,
                                                 const float* __restrict__ c1) {
    __shared__ float part[4][4][RANK];            // [warp][tok][r]

    const int warp = threadIdx.x >> 5;
    const int lane = threadIdx.x & 31;
    const int token0 = blockIdx.x * 4;

    const float4* xp = reinterpret_cast<const float4*>(x)
                     + (size_t)token0 * (IN_F / 4) + warp * 256;
    const float4* cp = reinterpret_cast<const float4*>(c1) + warp * 256;

    float acc[4][RANK];
#pragma unroll
    for (int t = 0; t < 4; t++)
#pragma unroll
        for (int r = 0; r < RANK; r++) acc[t][r] = 0.0f;

    // 256 float4 per warp-quarter, 32 lanes -> 8 iterations
#pragma unroll 2
    for (int i = lane; i < 256; i += 32) {
        float4 xv[4];
#pragma unroll
        for (int t = 0; t < 4; t++)
            xv[t] = __ldcv(xp + (size_t)t * (IN_F / 4) + i);   // LDG.cv
#pragma unroll
        for (int r = 0; r < RANK; r++) {
            const float4 c = __ldg(cp + (size_t)r * (IN_F / 4) + i);
#pragma unroll
            for (int t = 0; t < 4; t++) {
                acc[t][r] += xv[t].x * c.x + xv[t].y * c.y
                           + xv[t].z * c.z + xv[t].w * c.w;
            }
        }
    }

#pragma unroll
    for (int t = 0; t < 4; t++)
#pragma unroll
        for (int r = 0; r < RANK; r++) {
            float v = acc[t][r];
#pragma unroll
            for (int off = 16; off; off >>= 1)
                v += __shfl_xor_sync(0xffffffffu, v, off);
            if (lane == 0) part[warp][t][r] = v;
        }
    __syncthreads();

    if (threadIdx.x < 4 * RANK) {
        const int t = threadIdx.x >> 3;
        const int r = threadIdx.x & 7;
        g_t[(size_t)(token0 + t) * RANK + r] =
            part[0][t][r] + part[1][t][r] + part[2][t][r] + part[3][t][r];
    }
}

// ---------------------------------------------------------------------------
// Stage 2: y[tok, o] = bias[o] + sum_r t[tok, r] * core0[o, r]
// Best-known body (25.6us): 64 tokens x 1024 outputs per block, t via
// LDS.128 float4 pairs, c0 coeffs in regs, STG.128 evict-first stores.
// ---------------------------------------------------------------------------
__global__ void __launch_bounds__(256) tt_stage2(const float* __restrict__ c0,
                                                 const float* __restrict__ bias,
                                                 float* __restrict__ y) {
    __shared__ float4 ts[64 * 2];                 // t[64][8] as float4 pairs
    const int tid = threadIdx.x;
    const int token0 = blockIdx.y * 64;
    const int o = blockIdx.x * 1024 + tid * 4;

    if (tid < 128) {
        const float4* tg = reinterpret_cast<const float4*>(g_t + (size_t)token0 * RANK);
        ts[tid] = tg[tid];
    }

    float4 ca[4], cb[4];
#pragma unroll
    for (int j = 0; j < 4; j++) {
        const float4* c = reinterpret_cast<const float4*>(c0 + (size_t)(o + j) * RANK);
        ca[j] = __ldg(c);
        cb[j] = __ldg(c + 1);
    }
    const float4 bv = __ldg(reinterpret_cast<const float4*>(bias + o));

    __syncthreads();

#pragma unroll 4
    for (int tok = 0; tok < 64; tok++) {
        const float4 tA = ts[tok * 2];
        const float4 tB = ts[tok * 2 + 1];

        float4 res;
        res.x = bv.x + ca[0].x * tA.x + ca[0].y * tA.y + ca[0].z * tA.z + ca[0].w * tA.w
                     + cb[0].x * tB.x + cb[0].y * tB.y + cb[0].z * tB.z + cb[0].w * tB.w;
        res.y = bv.y + ca[1].x * tA.x + ca[1].y * tA.y + ca[1].z * tA.z + ca[1].w * tA.w
                     + cb[1].x * tB.x + cb[1].y * tB.y + cb[1].z * tB.z + cb[1].w * tB.w;
        res.z = bv.z + ca[2].x * tA.x + ca[2].y * tA.y + ca[2].z * tA.z + ca[2].w * tA.w
                     + cb[2].x * tB.x + cb[2].y * tB.y + cb[2].z * tB.z + cb[2].w * tB.w;
        res.w = bv.w + ca[3].x * tA.x + ca[3].y * tA.y + ca[3].z * tA.z + ca[3].w * tA.w
                     + cb[3].x * tB.x + cb[3].y * tB.y + cb[3].z * tB.z + cb[3].w * tB.w;

        __stcs(reinterpret_cast<float4*>(y + (size_t)(token0 + tok) * OUT_F + o),
               res);
    }
}

extern "C" void kernel_launch(void* const* d_in, const int* in_sizes, int n_in,
                              void* d_out, int out_size) {
    const float* x    = (const float*)d_in[0];   // [TOKENS, IN_F]
    const float* c0   = (const float*)d_in[1];   // [OUT_F, RANK]
    const float* c1   = (const float*)d_in[2];   // [RANK, IN_F]
    const float* bias = (const float*)d_in[3];   // [OUT_F]
    float* y = (float*)d_out;

    const int tokens = in_sizes[0] / IN_F;       // 8192

    // Stage 1: 4 tokens/block, 4 warps share them (quarter-row each)
    tt_stage1<<<tokens / 4, 128>>>(x, c1);

    // Stage 2: 4 output chunks x 64-token groups = 512 blocks
    dim3 g2(OUT_F / 1024, tokens / 64);
    tt_stage2<<<g2, 256>>>(c0, bias, y);
}